// round 1
// baseline (speedup 1.0000x reference)
#include <cuda_runtime.h>
#include <cuda_bf16.h>
#include <cstdint>

// Problem constants
#define BATCH 16
#define SEQ   1024
#define T     (BATCH * SEQ)      // 16384 serial steps
#define HID   600
#define IN    512                // 3 (tag emb) + 509 (context)
#define G3    1800               // 3*HID

// Recurrence config
#define NBLK  120                // persistent blocks (<= #SMs, co-resident)
#define IPB   5                  // hidden indices per block (NBLK*IPB = 600)
#define KC    19                 // k-chunk per lane (32*19 = 608 >= 600)
#define RTHREADS 160             // 5 warps = IPB warps

// ------------------- static device scratch (no allocations allowed) -------
__device__ float    d_X[(size_t)T * IN];        // 33.5 MB  built input
__device__ float    d_gx[(size_t)T * G3];       // 118 MB   precomputed gates
__device__ float    d_hf[2][640];               // ping-pong fwd hidden (padded)
__device__ float    d_hb[2][640];               // ping-pong bwd hidden (padded)
__device__ unsigned d_flags[NBLK * 32];         // 1 flag per block, 128B apart

// ------------------- memory-order helpers ---------------------------------
__device__ __forceinline__ unsigned ld_acq(const unsigned* p) {
    unsigned v;
    asm volatile("ld.global.acquire.gpu.b32 %0, [%1];" : "=r"(v) : "l"(p) : "memory");
    return v;
}
__device__ __forceinline__ void st_rel(unsigned* p, unsigned v) {
    asm volatile("st.global.release.gpu.b32 [%0], %1;" :: "l"(p), "r"(v) : "memory");
}
__device__ __forceinline__ float sigm(float x) {
    return 1.0f / (1.0f + __expf(-x));
}

// ------------------- kernel 0: init flags + h buffers ---------------------
__global__ void init_bufs() {
    int t = threadIdx.x + blockIdx.x * blockDim.x;
    float* hf = (float*)d_hf;
    float* hb = (float*)d_hb;
    if (t < 2 * 640) { hf[t] = 0.0f; hb[t] = 0.0f; }
    if (t < NBLK) d_flags[t * 32] = 0u;
}

// ------------------- kernel 1: build X = [tag_emb(tags), context] ---------
__global__ void build_x(const float* __restrict__ ctx,
                        const int* __restrict__ tags,
                        const float* __restrict__ emb) {
    int t = blockIdx.x;        // 0..16383
    int k = threadIdx.x;       // 0..511
    float v;
    if (k < 3) v = emb[tags[t] * 3 + k];
    else       v = ctx[(size_t)t * 509 + (k - 3)];
    d_X[(size_t)t * IN + k] = v;
}

// ------------------- kernel 2: gx = X @ W_ih^T + b_ih ---------------------
// A [M=16384, K=512] row-major, B = W_ih [N=1800, K=512] row-major (NT gemm)
#define BM 128
#define BN 128
#define BKK 16
__global__ __launch_bounds__(256) void gemm_gx(const float* __restrict__ Wih,
                                               const float* __restrict__ bih) {
    __shared__ float As[BKK][BM];
    __shared__ float Bs[BKK][BN];
    int tid = threadIdx.x;
    int bm = blockIdx.x * BM;
    int bn = blockIdx.y * BN;
    int tx = tid & 15;       // 0..15 -> n
    int ty = tid >> 4;       // 0..15 -> m
    float acc[8][8];
#pragma unroll
    for (int r = 0; r < 8; r++)
#pragma unroll
        for (int c = 0; c < 8; c++) acc[r][c] = 0.0f;

    for (int k0 = 0; k0 < IN; k0 += BKK) {
        // load A tile (128 x 16), 2 float4 per thread
#pragma unroll
        for (int i = 0; i < 2; i++) {
            int id = tid + i * 256;
            int m  = id >> 2;
            int kq = (id & 3) * 4;
            float4 v = *(const float4*)&d_X[(size_t)(bm + m) * IN + k0 + kq];
            As[kq + 0][m] = v.x; As[kq + 1][m] = v.y;
            As[kq + 2][m] = v.z; As[kq + 3][m] = v.w;
        }
        // load B tile (128 x 16) with N guard
#pragma unroll
        for (int i = 0; i < 2; i++) {
            int id = tid + i * 256;
            int n  = id >> 2;
            int kq = (id & 3) * 4;
            int j  = bn + n;
            float4 v = make_float4(0.f, 0.f, 0.f, 0.f);
            if (j < G3) v = *(const float4*)&Wih[(size_t)j * IN + k0 + kq];
            Bs[kq + 0][n] = v.x; Bs[kq + 1][n] = v.y;
            Bs[kq + 2][n] = v.z; Bs[kq + 3][n] = v.w;
        }
        __syncthreads();
#pragma unroll
        for (int kk = 0; kk < BKK; kk++) {
            float a[8], b[8];
#pragma unroll
            for (int u = 0; u < 4; u++) {
                a[u]     = As[kk][ty * 4 + u];
                a[4 + u] = As[kk][64 + ty * 4 + u];
                b[u]     = Bs[kk][tx * 4 + u];
                b[4 + u] = Bs[kk][64 + tx * 4 + u];
            }
#pragma unroll
            for (int r = 0; r < 8; r++)
#pragma unroll
                for (int c = 0; c < 8; c++) acc[r][c] += a[r] * b[c];
        }
        __syncthreads();
    }
    // store + bias, guard j < 1800
#pragma unroll
    for (int r = 0; r < 8; r++) {
        int m = bm + ((r < 4) ? (ty * 4 + r) : (64 + ty * 4 + (r - 4)));
#pragma unroll
        for (int c = 0; c < 8; c++) {
            int j = bn + ((c < 4) ? (tx * 4 + c) : (64 + tx * 4 + (c - 4)));
            if (j < G3)
                d_gx[(size_t)m * G3 + j] = acc[r][c] + __ldg(&bih[j]);
        }
    }
}

// ------------------- kernel 3: persistent bidirectional GRU recurrence ----
// Block blk owns hidden indices i = blk*IPB + w (w = warp id, 0..4).
// Warp layout: lane l covers k in [l*KC, l*KC+KC). Weights live in registers.
__global__ void __launch_bounds__(RTHREADS, 1)
gru_recur(const float* __restrict__ Whh,
          const float* __restrict__ bhh,
          float* __restrict__ out) {
    int tid  = threadIdx.x;
    int w    = tid >> 5;
    int lane = tid & 31;
    int blk  = blockIdx.x;
    int i    = blk * IPB + w;
    int k0   = lane * KC;

    // --- load this thread's W_hh slice into registers (zero-padded) ---
    float wr[KC], wz[KC], wn[KC];
#pragma unroll
    for (int j = 0; j < KC; j++) {
        int k = k0 + j;
        bool ok = (k < HID);
        wr[j] = ok ? Whh[(size_t)(0 * HID + i) * HID + k] : 0.0f;
        wz[j] = ok ? Whh[(size_t)(1 * HID + i) * HID + k] : 0.0f;
        wn[j] = ok ? Whh[(size_t)(2 * HID + i) * HID + k] : 0.0f;
    }
    float bhr = 0.f, bhz = 0.f, bhn = 0.f;
    if (lane == 0) {
        bhr = bhh[i];
        bhz = bhh[HID + i];
        bhn = bhh[2 * HID + i];
    }

    // --- prefetch gx for step 0 (fwd row 0, bwd row 1023) ---
    float pgf0 = 0.f, pgf1 = 0.f, pgf2 = 0.f;
    float pgb0 = 0.f, pgb1 = 0.f, pgb2 = 0.f;
    if (lane == 0) {
        const float* gf = &d_gx[(size_t)0 * G3];
        const float* gb = &d_gx[(size_t)1023 * G3];
        pgf0 = __ldcg(gf + i); pgf1 = __ldcg(gf + HID + i); pgf2 = __ldcg(gf + 2 * HID + i);
        pgb0 = __ldcg(gb + i); pgb1 = __ldcg(gb + HID + i); pgb2 = __ldcg(gb + 2 * HID + i);
    }

    for (int s = 0; s < T; s++) {
        // grid barrier: wait for all blocks to have completed step s-1
        if (s > 0 && tid < NBLK) {
            while (ld_acq(&d_flags[tid * 32]) < (unsigned)s) { }
        }
        __syncthreads();

        const float* hf = d_hf[s & 1];
        const float* hb = d_hb[s & 1];

        // load h chunks (L1-bypassing: other SMs wrote them)
        float hfv[KC], hbv[KC];
#pragma unroll
        for (int j = 0; j < KC; j++) {
            hfv[j] = __ldcg(hf + k0 + j);
            hbv[j] = __ldcg(hb + k0 + j);
        }

        // consume prefetched gx, own h[i], and prefetch next step's gx
        float gf0 = pgf0, gf1 = pgf1, gf2 = pgf2;
        float gb0 = pgb0, gb1 = pgb1, gb2 = pgb2;
        float hfi = 0.f, hbi = 0.f;
        if (lane == 0) {
            hfi = __ldcg(hf + i);
            hbi = __ldcg(hb + i);
            if (s + 1 < T) {
                int sn  = s + 1;
                int sp  = sn & 1023;
                int rbn = sn + 1023 - 2 * sp;   // reversed row for bwd
                const float* gf = &d_gx[(size_t)sn  * G3];
                const float* gb = &d_gx[(size_t)rbn * G3];
                pgf0 = __ldcg(gf + i); pgf1 = __ldcg(gf + HID + i); pgf2 = __ldcg(gf + 2 * HID + i);
                pgb0 = __ldcg(gb + i); pgb1 = __ldcg(gb + HID + i); pgb2 = __ldcg(gb + 2 * HID + i);
            }
        }

        // partial dot products: gh = W_hh . h (both directions)
        float af = 0.f, zf = 0.f, nf = 0.f;
        float ab = 0.f, zb = 0.f, nb = 0.f;
#pragma unroll
        for (int j = 0; j < KC; j++) {
            af += wr[j] * hfv[j];
            zf += wz[j] * hfv[j];
            nf += wn[j] * hfv[j];
            ab += wr[j] * hbv[j];
            zb += wz[j] * hbv[j];
            nb += wn[j] * hbv[j];
        }
        // warp reduce (lanes = k-groups)
#pragma unroll
        for (int o = 16; o; o >>= 1) {
            af += __shfl_down_sync(0xffffffffu, af, o);
            zf += __shfl_down_sync(0xffffffffu, zf, o);
            nf += __shfl_down_sync(0xffffffffu, nf, o);
            ab += __shfl_down_sync(0xffffffffu, ab, o);
            zb += __shfl_down_sync(0xffffffffu, zb, o);
            nb += __shfl_down_sync(0xffffffffu, nb, o);
        }

        if (lane == 0) {
            // forward update
            float r_ = sigm(gf0 + af + bhr);
            float z_ = sigm(gf1 + zf + bhz);
            float n_ = tanhf(gf2 + r_ * (nf + bhn));
            float hn = (1.0f - z_) * n_ + z_ * hfi;
            d_hf[(s + 1) & 1][i] = hn;
            // backward update
            float rB = sigm(gb0 + ab + bhr);
            float zB = sigm(gb1 + zb + bhz);
            float nB = tanhf(gb2 + rB * (nb + bhn));
            float hB = (1.0f - zB) * nB + zB * hbi;
            d_hb[(s + 1) & 1][i] = hB;
            if (s == T - 1) {
                out[i]       = hn;
                out[HID + i] = hB;
            }
        }
        __syncthreads();
        if (tid == 0) st_rel(&d_flags[blk * 32], (unsigned)(s + 1));
    }
}

// ------------------- launch ------------------------------------------------
extern "C" void kernel_launch(void* const* d_in, const int* in_sizes, int n_in,
                              void* d_out, int out_size) {
    const float* context = (const float*)d_in[0];   // [16,1024,509]
    const int*   tags    = (const int*)  d_in[1];   // [16,1024]
    const float* tag_emb = (const float*)d_in[2];   // [3,3]
    const float* W_ih    = (const float*)d_in[3];   // [1800,512]
    const float* W_hh    = (const float*)d_in[4];   // [1800,600]
    const float* b_ih    = (const float*)d_in[5];   // [1800]
    const float* b_hh    = (const float*)d_in[6];   // [1800]
    float*       out     = (float*)d_out;           // [1200]

    init_bufs<<<2, 640>>>();
    build_x<<<T, IN>>>(context, tags, tag_emb);
    dim3 g((T + BM - 1) / BM, (G3 + BN - 1) / BN);  // 128 x 15
    gemm_gx<<<g, 256>>>(W_ih, b_ih);
    gru_recur<<<NBLK, RTHREADS>>>(W_hh, b_hh, out);
}

// round 2
// speedup vs baseline: 5.2509x; 5.2509x over previous
#include <cuda_runtime.h>
#include <cuda_bf16.h>
#include <cstdint>

// Problem constants
#define BATCH 16
#define SEQ   1024
#define T     (BATCH * SEQ)      // 16384 serial steps
#define HID   600
#define IN    512                // 3 (tag emb) + 509 (context)
#define G3    1800               // 3*HID

// Recurrence config
#define NBLK  120                // persistent blocks (one per SM)
#define IPB   5                  // hidden indices per block (NBLK*IPB = 600)
#define RTHREADS 160             // 5 warps = IPB warps
#define KC    20                 // 5 float4 chunks per lane: k = lane*4 + c*128 (covers 640)

// ------------------- static device scratch (no allocations allowed) -------
__device__ float    d_X[(size_t)T * IN];        // 33.5 MB  built input
__device__ float    d_gx[(size_t)T * G3];       // 118 MB   precomputed gates
__device__ __align__(16) float d_hf[2][640];    // ping-pong fwd hidden (padded)
__device__ __align__(16) float d_hb[2][640];    // ping-pong bwd hidden (padded)
__device__ unsigned d_count;                    // barrier arrival counter
__device__ unsigned d_epoch;                    // barrier epoch word

// ------------------- memory-order helpers ---------------------------------
__device__ __forceinline__ unsigned ld_acq(const unsigned* p) {
    unsigned v;
    asm volatile("ld.global.acquire.gpu.b32 %0, [%1];" : "=r"(v) : "l"(p) : "memory");
    return v;
}
__device__ __forceinline__ void st_rel(unsigned* p, unsigned v) {
    asm volatile("st.global.release.gpu.b32 [%0], %1;" :: "l"(p), "r"(v) : "memory");
}
__device__ __forceinline__ float sigm(float x) {
    return 1.0f / (1.0f + __expf(-x));
}

// ------------------- kernel 0: init barrier + h buffers -------------------
__global__ void init_bufs() {
    int t = threadIdx.x + blockIdx.x * blockDim.x;
    float* hf = (float*)d_hf;
    float* hb = (float*)d_hb;
    if (t < 2 * 640) { hf[t] = 0.0f; hb[t] = 0.0f; }
    if (t == 0) { d_count = 0u; d_epoch = 0u; }
}

// ------------------- kernel 1: build X = [tag_emb(tags), context] ---------
__global__ void build_x(const float* __restrict__ ctx,
                        const int* __restrict__ tags,
                        const float* __restrict__ emb) {
    int t = blockIdx.x;        // 0..16383
    int k = threadIdx.x;       // 0..511
    float v;
    if (k < 3) v = emb[tags[t] * 3 + k];
    else       v = ctx[(size_t)t * 509 + (k - 3)];
    d_X[(size_t)t * IN + k] = v;
}

// ------------------- kernel 2: gx = X @ W_ih^T + b_ih ---------------------
// A [M=16384, K=512] row-major, B = W_ih [N=1800, K=512] row-major (NT gemm)
#define BM 128
#define BN 128
#define BKK 16
__global__ __launch_bounds__(256) void gemm_gx(const float* __restrict__ Wih,
                                               const float* __restrict__ bih) {
    __shared__ float As[BKK][BM];
    __shared__ float Bs[BKK][BN];
    int tid = threadIdx.x;
    int bm = blockIdx.x * BM;
    int bn = blockIdx.y * BN;
    int tx = tid & 15;       // 0..15 -> n
    int ty = tid >> 4;       // 0..15 -> m
    float acc[8][8];
#pragma unroll
    for (int r = 0; r < 8; r++)
#pragma unroll
        for (int c = 0; c < 8; c++) acc[r][c] = 0.0f;

    for (int k0 = 0; k0 < IN; k0 += BKK) {
#pragma unroll
        for (int i = 0; i < 2; i++) {
            int id = tid + i * 256;
            int m  = id >> 2;
            int kq = (id & 3) * 4;
            float4 v = *(const float4*)&d_X[(size_t)(bm + m) * IN + k0 + kq];
            As[kq + 0][m] = v.x; As[kq + 1][m] = v.y;
            As[kq + 2][m] = v.z; As[kq + 3][m] = v.w;
        }
#pragma unroll
        for (int i = 0; i < 2; i++) {
            int id = tid + i * 256;
            int n  = id >> 2;
            int kq = (id & 3) * 4;
            int j  = bn + n;
            float4 v = make_float4(0.f, 0.f, 0.f, 0.f);
            if (j < G3) v = *(const float4*)&Wih[(size_t)j * IN + k0 + kq];
            Bs[kq + 0][n] = v.x; Bs[kq + 1][n] = v.y;
            Bs[kq + 2][n] = v.z; Bs[kq + 3][n] = v.w;
        }
        __syncthreads();
#pragma unroll
        for (int kk = 0; kk < BKK; kk++) {
            float a[8], b[8];
#pragma unroll
            for (int u = 0; u < 4; u++) {
                a[u]     = As[kk][ty * 4 + u];
                a[4 + u] = As[kk][64 + ty * 4 + u];
                b[u]     = Bs[kk][tx * 4 + u];
                b[4 + u] = Bs[kk][64 + tx * 4 + u];
            }
#pragma unroll
            for (int r = 0; r < 8; r++)
#pragma unroll
                for (int c = 0; c < 8; c++) acc[r][c] += a[r] * b[c];
        }
        __syncthreads();
    }
#pragma unroll
    for (int r = 0; r < 8; r++) {
        int m = bm + ((r < 4) ? (ty * 4 + r) : (64 + ty * 4 + (r - 4)));
#pragma unroll
        for (int c = 0; c < 8; c++) {
            int j = bn + ((c < 4) ? (tx * 4 + c) : (64 + tx * 4 + (c - 4)));
            if (j < G3)
                d_gx[(size_t)m * G3 + j] = acc[r][c] + __ldg(&bih[j]);
        }
    }
}

// ------------------- kernel 3: persistent bidirectional GRU recurrence ----
// Block blk owns hidden indices i = blk*IPB + w (w = warp id, 0..4).
// Lane l covers k = l*4 + c*128, c in [0,5). Weights live in registers.
__global__ void __launch_bounds__(RTHREADS, 1)
gru_recur(const float* __restrict__ Whh,
          const float* __restrict__ bhh,
          float* __restrict__ out) {
    int tid  = threadIdx.x;
    int w    = tid >> 5;
    int lane = tid & 31;
    int blk  = blockIdx.x;
    int i    = blk * IPB + w;

    // --- load this thread's W_hh slice into registers (zero-padded) ---
    float wr[KC], wz[KC], wn[KC];
#pragma unroll
    for (int c = 0; c < 5; c++) {
#pragma unroll
        for (int u = 0; u < 4; u++) {
            int k = c * 128 + lane * 4 + u;
            bool ok = (k < HID);
            wr[c * 4 + u] = ok ? Whh[(size_t)(0 * HID + i) * HID + k] : 0.0f;
            wz[c * 4 + u] = ok ? Whh[(size_t)(1 * HID + i) * HID + k] : 0.0f;
            wn[c * 4 + u] = ok ? Whh[(size_t)(2 * HID + i) * HID + k] : 0.0f;
        }
    }
    float bhr = 0.f, bhz = 0.f, bhn = 0.f;
    if (lane == 0) {
        bhr = bhh[i];
        bhz = bhh[HID + i];
        bhn = bhh[2 * HID + i];
    }

    // --- prefetch gx for step 0 (fwd row 0, bwd row 1023) ---
    float pgf0 = 0.f, pgf1 = 0.f, pgf2 = 0.f;
    float pgb0 = 0.f, pgb1 = 0.f, pgb2 = 0.f;
    if (lane == 0) {
        const float* gf = &d_gx[(size_t)0 * G3];
        const float* gb = &d_gx[(size_t)1023 * G3];
        pgf0 = __ldcg(gf + i); pgf1 = __ldcg(gf + HID + i); pgf2 = __ldcg(gf + 2 * HID + i);
        pgb0 = __ldcg(gb + i); pgb1 = __ldcg(gb + HID + i); pgb2 = __ldcg(gb + 2 * HID + i);
    }

    for (int s = 0; s < T; s++) {
        const float4* hf4 = (const float4*)d_hf[s & 1];
        const float4* hb4 = (const float4*)d_hb[s & 1];
        const float*  hf  = d_hf[s & 1];
        const float*  hb  = d_hb[s & 1];

        // lane 0: own h[i] + prefetch next step's gx (long-latency, issue first)
        float gf0 = pgf0, gf1 = pgf1, gf2 = pgf2;
        float gb0 = pgb0, gb1 = pgb1, gb2 = pgb2;
        float hfi = 0.f, hbi = 0.f;
        if (lane == 0) {
            hfi = __ldcg(hf + i);
            hbi = __ldcg(hb + i);
            if (s + 1 < T) {
                int sn  = s + 1;
                int sp  = sn & 1023;
                int rbn = sn + 1023 - 2 * sp;   // reversed row for bwd
                const float* gfn = &d_gx[(size_t)sn  * G3];
                const float* gbn = &d_gx[(size_t)rbn * G3];
                pgf0 = __ldcg(gfn + i); pgf1 = __ldcg(gfn + HID + i); pgf2 = __ldcg(gfn + 2 * HID + i);
                pgb0 = __ldcg(gbn + i); pgb1 = __ldcg(gbn + HID + i); pgb2 = __ldcg(gbn + 2 * HID + i);
            }
        }

        // vectorized h broadcast loads + partial dot products (both dirs)
        float af = 0.f, zf = 0.f, nf = 0.f;
        float ab = 0.f, zb = 0.f, nb = 0.f;
#pragma unroll
        for (int c = 0; c < 5; c++) {
            float4 hfv = __ldcg(&hf4[c * 32 + lane]);
            float4 hbv = __ldcg(&hb4[c * 32 + lane]);
            const float* WR = &wr[c * 4];
            const float* WZ = &wz[c * 4];
            const float* WN = &wn[c * 4];
            af += WR[0] * hfv.x + WR[1] * hfv.y + WR[2] * hfv.z + WR[3] * hfv.w;
            zf += WZ[0] * hfv.x + WZ[1] * hfv.y + WZ[2] * hfv.z + WZ[3] * hfv.w;
            nf += WN[0] * hfv.x + WN[1] * hfv.y + WN[2] * hfv.z + WN[3] * hfv.w;
            ab += WR[0] * hbv.x + WR[1] * hbv.y + WR[2] * hbv.z + WR[3] * hbv.w;
            zb += WZ[0] * hbv.x + WZ[1] * hbv.y + WZ[2] * hbv.z + WZ[3] * hbv.w;
            nb += WN[0] * hbv.x + WN[1] * hbv.y + WN[2] * hbv.z + WN[3] * hbv.w;
        }

        // warp reduce
#pragma unroll
        for (int o = 16; o; o >>= 1) {
            af += __shfl_down_sync(0xffffffffu, af, o);
            zf += __shfl_down_sync(0xffffffffu, zf, o);
            nf += __shfl_down_sync(0xffffffffu, nf, o);
            ab += __shfl_down_sync(0xffffffffu, ab, o);
            zb += __shfl_down_sync(0xffffffffu, zb, o);
            nb += __shfl_down_sync(0xffffffffu, nb, o);
        }

        if (lane == 0) {
            // forward update
            float r_ = sigm(gf0 + af + bhr);
            float z_ = sigm(gf1 + zf + bhz);
            float n_ = tanhf(gf2 + r_ * (nf + bhn));
            float hn = (1.0f - z_) * n_ + z_ * hfi;
            d_hf[(s + 1) & 1][i] = hn;
            // backward update
            float rB = sigm(gb0 + ab + bhr);
            float zB = sigm(gb1 + zb + bhz);
            float nB = tanhf(gb2 + rB * (nb + bhn));
            float hB = (1.0f - zB) * nB + zB * hbi;
            d_hb[(s + 1) & 1][i] = hB;
            if (s == T - 1) {
                out[i]       = hn;
                out[HID + i] = hB;
            }
        }

        // ---- counter+epoch grid barrier (1 atomic / block, 1 poller / block)
        if (s + 1 < T) {
            __syncthreads();
            if (tid == 0) {
                __threadfence();                       // publish h stores
                unsigned old = atomicAdd(&d_count, 1u);
                if (old == (unsigned)(s + 1) * NBLK - 1u) {
                    __threadfence();                   // acquire others' stores
                    st_rel(&d_epoch, (unsigned)(s + 1));
                }
                while (ld_acq(&d_epoch) < (unsigned)(s + 1)) { }
            }
            __syncthreads();
        }
    }
}

// ------------------- launch ------------------------------------------------
extern "C" void kernel_launch(void* const* d_in, const int* in_sizes, int n_in,
                              void* d_out, int out_size) {
    const float* context = (const float*)d_in[0];   // [16,1024,509]
    const int*   tags    = (const int*)  d_in[1];   // [16,1024]
    const float* tag_emb = (const float*)d_in[2];   // [3,3]
    const float* W_ih    = (const float*)d_in[3];   // [1800,512]
    const float* W_hh    = (const float*)d_in[4];   // [1800,600]
    const float* b_ih    = (const float*)d_in[5];   // [1800]
    const float* b_hh    = (const float*)d_in[6];   // [1800]
    float*       out     = (float*)d_out;           // [1200]

    init_bufs<<<2, 640>>>();
    build_x<<<T, IN>>>(context, tags, tag_emb);
    dim3 g((T + BM - 1) / BM, (G3 + BN - 1) / BN);  // 128 x 15
    gemm_gx<<<g, 256>>>(W_ih, b_ih);
    gru_recur<<<NBLK, RTHREADS>>>(W_hh, b_hh, out);
}

// round 3
// speedup vs baseline: 6.9569x; 1.3249x over previous
#include <cuda_runtime.h>
#include <cuda_bf16.h>
#include <cstdint>

// Problem constants
#define BATCH 16
#define SEQ   1024
#define T     (BATCH * SEQ)      // 16384 serial steps
#define HID   600
#define IN    512                // 3 (tag emb) + 509 (context)
#define G3    1800               // 3*HID

// Recurrence config
#define NBLK  120                // persistent blocks (one per SM)
#define IPB   5                  // hidden indices per block (NBLK*IPB = 600)
#define RTHREADS 320             // 10 warps: 5 fwd + 5 bwd
#define H4    160                // 640 floats = 160 float4 per h buffer

// ------------------- static device scratch (no allocations allowed) -------
__device__ float    d_X[(size_t)T * IN];        // 33.5 MB  built input
__device__ float    d_gx[(size_t)T * G3];       // 118 MB   precomputed gates
__device__ __align__(16) float d_hf[2][640];    // ping-pong fwd hidden (padded)
__device__ __align__(16) float d_hb[2][640];    // ping-pong bwd hidden (padded)
__device__ unsigned d_count[32];                // barrier arrival counter (own line)
__device__ unsigned d_epoch[32];                // barrier epoch word (own line)

// ------------------- memory-order helpers ---------------------------------
__device__ __forceinline__ unsigned ld_acq(const unsigned* p) {
    unsigned v;
    asm volatile("ld.global.acquire.gpu.b32 %0, [%1];" : "=r"(v) : "l"(p) : "memory");
    return v;
}
__device__ __forceinline__ void st_rel(unsigned* p, unsigned v) {
    asm volatile("st.global.release.gpu.b32 [%0], %1;" :: "l"(p), "r"(v) : "memory");
}
__device__ __forceinline__ float sigm(float x) {
    return 1.0f / (1.0f + __expf(-x));
}
__device__ __forceinline__ float tanh_fast(float x) {
    x = fminf(15.0f, fmaxf(-15.0f, x));
    float e = __expf(2.0f * x);
    return __fdividef(e - 1.0f, e + 1.0f);
}

// ------------------- kernel 0: init barrier + h buffers -------------------
__global__ void init_bufs() {
    int t = threadIdx.x + blockIdx.x * blockDim.x;
    float* hf = (float*)d_hf;
    float* hb = (float*)d_hb;
    if (t < 2 * 640) { hf[t] = 0.0f; hb[t] = 0.0f; }
    if (t == 0) { d_count[0] = 0u; d_epoch[0] = 0u; }
}

// ------------------- kernel 1: build X = [tag_emb(tags), context] ---------
__global__ void build_x(const float* __restrict__ ctx,
                        const int* __restrict__ tags,
                        const float* __restrict__ emb) {
    int t = blockIdx.x;        // 0..16383
    int k = threadIdx.x;       // 0..511
    float v;
    if (k < 3) v = emb[tags[t] * 3 + k];
    else       v = ctx[(size_t)t * 509 + (k - 3)];
    d_X[(size_t)t * IN + k] = v;
}

// ------------------- kernel 2: gx = X @ W_ih^T + b_ih ---------------------
#define BM 128
#define BN 128
#define BKK 16
__global__ __launch_bounds__(256) void gemm_gx(const float* __restrict__ Wih,
                                               const float* __restrict__ bih) {
    __shared__ float As[BKK][BM];
    __shared__ float Bs[BKK][BN];
    int tid = threadIdx.x;
    int bm = blockIdx.x * BM;
    int bn = blockIdx.y * BN;
    int tx = tid & 15;
    int ty = tid >> 4;
    float acc[8][8];
#pragma unroll
    for (int r = 0; r < 8; r++)
#pragma unroll
        for (int c = 0; c < 8; c++) acc[r][c] = 0.0f;

    for (int k0 = 0; k0 < IN; k0 += BKK) {
#pragma unroll
        for (int i = 0; i < 2; i++) {
            int id = tid + i * 256;
            int m  = id >> 2;
            int kq = (id & 3) * 4;
            float4 v = *(const float4*)&d_X[(size_t)(bm + m) * IN + k0 + kq];
            As[kq + 0][m] = v.x; As[kq + 1][m] = v.y;
            As[kq + 2][m] = v.z; As[kq + 3][m] = v.w;
        }
#pragma unroll
        for (int i = 0; i < 2; i++) {
            int id = tid + i * 256;
            int n  = id >> 2;
            int kq = (id & 3) * 4;
            int j  = bn + n;
            float4 v = make_float4(0.f, 0.f, 0.f, 0.f);
            if (j < G3) v = *(const float4*)&Wih[(size_t)j * IN + k0 + kq];
            Bs[kq + 0][n] = v.x; Bs[kq + 1][n] = v.y;
            Bs[kq + 2][n] = v.z; Bs[kq + 3][n] = v.w;
        }
        __syncthreads();
#pragma unroll
        for (int kk = 0; kk < BKK; kk++) {
            float a[8], b[8];
#pragma unroll
            for (int u = 0; u < 4; u++) {
                a[u]     = As[kk][ty * 4 + u];
                a[4 + u] = As[kk][64 + ty * 4 + u];
                b[u]     = Bs[kk][tx * 4 + u];
                b[4 + u] = Bs[kk][64 + tx * 4 + u];
            }
#pragma unroll
            for (int r = 0; r < 8; r++)
#pragma unroll
                for (int c = 0; c < 8; c++) acc[r][c] += a[r] * b[c];
        }
        __syncthreads();
    }
#pragma unroll
    for (int r = 0; r < 8; r++) {
        int m = bm + ((r < 4) ? (ty * 4 + r) : (64 + ty * 4 + (r - 4)));
#pragma unroll
        for (int c = 0; c < 8; c++) {
            int j = bn + ((c < 4) ? (tx * 4 + c) : (64 + tx * 4 + (c - 4)));
            if (j < G3)
                d_gx[(size_t)m * G3 + j] = acc[r][c] + __ldg(&bih[j]);
        }
    }
}

// ------------------- kernel 3: persistent bidirectional GRU recurrence ----
// 10 warps: warp w in [0,5) -> forward output i = blk*5 + w
//           warp w in [5,10) -> backward output i = blk*5 + (w-5)
// h staged into SMEM once per block per step; dots read SMEM.
__global__ void __launch_bounds__(RTHREADS, 1)
gru_recur(const float* __restrict__ Whh,
          const float* __restrict__ bhh,
          float* __restrict__ out) {
    __shared__ __align__(16) float s_h[2 * 640];   // [0,640)=fwd, [640,1280)=bwd

    int tid  = threadIdx.x;
    int w    = tid >> 5;
    int lane = tid & 31;
    int blk  = blockIdx.x;
    bool fwd = (w < 5);
    int wl   = fwd ? w : (w - 5);
    int i    = blk * IPB + wl;

    // --- load this warp's W_hh rows into registers (zero-padded) ---
    // k layout: k = c*128 + lane*4 + u, c in [0,5)
    float wr[20], wz[20], wn[20];
#pragma unroll
    for (int c = 0; c < 5; c++) {
#pragma unroll
        for (int u = 0; u < 4; u++) {
            int k = c * 128 + lane * 4 + u;
            bool ok = (k < HID);
            wr[c * 4 + u] = ok ? Whh[(size_t)(0 * HID + i) * HID + k] : 0.0f;
            wz[c * 4 + u] = ok ? Whh[(size_t)(1 * HID + i) * HID + k] : 0.0f;
            wn[c * 4 + u] = ok ? Whh[(size_t)(2 * HID + i) * HID + k] : 0.0f;
        }
    }
    float bhr = 0.f, bhz = 0.f, bhn = 0.f;
    if (lane == 0) {
        bhr = bhh[i];
        bhz = bhh[HID + i];
        bhn = bhh[2 * HID + i];
    }

    // --- prefetch gx for step 0 ---
    float pg0 = 0.f, pg1 = 0.f, pg2 = 0.f;
    if (lane == 0) {
        const float* g = fwd ? &d_gx[(size_t)0 * G3] : &d_gx[(size_t)1023 * G3];
        pg0 = __ldcg(g + i); pg1 = __ldcg(g + HID + i); pg2 = __ldcg(g + 2 * HID + i);
    }

    for (int s = 0; s < T; s++) {
        // ---- stage h (both dirs) into SMEM: 320 float4 = one per thread ----
        {
            const float4* hf4 = (const float4*)d_hf[s & 1];
            const float4* hb4 = (const float4*)d_hb[s & 1];
            float4 v = (tid < H4) ? __ldcg(&hf4[tid]) : __ldcg(&hb4[tid - H4]);
            ((float4*)s_h)[tid] = v;
        }

        // lane 0: prefetch next step's gx (long latency; overlap with sync+dots)
        float g0 = pg0, g1 = pg1, g2 = pg2;
        if (lane == 0 && s + 1 < T) {
            int sn  = s + 1;
            int row = fwd ? sn : (sn + 1023 - 2 * (sn & 1023));
            const float* g = &d_gx[(size_t)row * G3];
            pg0 = __ldcg(g + i); pg1 = __ldcg(g + HID + i); pg2 = __ldcg(g + 2 * HID + i);
        }

        __syncthreads();

        // ---- dot products from SMEM ----
        const float* hs = fwd ? s_h : (s_h + 640);
        float a = 0.f, z = 0.f, n = 0.f;
#pragma unroll
        for (int c = 0; c < 5; c++) {
            float4 hv = *(const float4*)&hs[c * 128 + lane * 4];
            const float* WR = &wr[c * 4];
            const float* WZ = &wz[c * 4];
            const float* WN = &wn[c * 4];
            a += WR[0] * hv.x + WR[1] * hv.y + WR[2] * hv.z + WR[3] * hv.w;
            z += WZ[0] * hv.x + WZ[1] * hv.y + WZ[2] * hv.z + WZ[3] * hv.w;
            n += WN[0] * hv.x + WN[1] * hv.y + WN[2] * hv.z + WN[3] * hv.w;
        }
#pragma unroll
        for (int o = 16; o; o >>= 1) {
            a += __shfl_down_sync(0xffffffffu, a, o);
            z += __shfl_down_sync(0xffffffffu, z, o);
            n += __shfl_down_sync(0xffffffffu, n, o);
        }

        if (lane == 0) {
            float hi = hs[i];
            float r_ = sigm(g0 + a + bhr);
            float z_ = sigm(g1 + z + bhz);
            float n_ = tanh_fast(g2 + r_ * (n + bhn));
            float hn = (1.0f - z_) * n_ + z_ * hi;
            if (fwd) d_hf[(s + 1) & 1][i] = hn;
            else     d_hb[(s + 1) & 1][i] = hn;
            if (s == T - 1) {
                if (fwd) out[i]       = hn;
                else     out[HID + i] = hn;
            }
        }

        // ---- counter+epoch grid barrier ----
        if (s + 1 < T) {
            __syncthreads();
            if (tid == 0) {
                __threadfence();                       // publish h stores (cumulative)
                unsigned old = atomicAdd(&d_count[0], 1u);
                if (old == (unsigned)(s + 1) * NBLK - 1u) {
                    st_rel(&d_epoch[0], (unsigned)(s + 1));
                }
                while (ld_acq(&d_epoch[0]) < (unsigned)(s + 1)) { }
            }
            __syncthreads();
        }
    }
}

// ------------------- launch ------------------------------------------------
extern "C" void kernel_launch(void* const* d_in, const int* in_sizes, int n_in,
                              void* d_out, int out_size) {
    const float* context = (const float*)d_in[0];   // [16,1024,509]
    const int*   tags    = (const int*)  d_in[1];   // [16,1024]
    const float* tag_emb = (const float*)d_in[2];   // [3,3]
    const float* W_ih    = (const float*)d_in[3];   // [1800,512]
    const float* W_hh    = (const float*)d_in[4];   // [1800,600]
    const float* b_ih    = (const float*)d_in[5];   // [1800]
    const float* b_hh    = (const float*)d_in[6];   // [1800]
    float*       out     = (float*)d_out;           // [1200]

    init_bufs<<<2, 640>>>();
    build_x<<<T, IN>>>(context, tags, tag_emb);
    dim3 g((T + BM - 1) / BM, (G3 + BN - 1) / BN);  // 128 x 15
    gemm_gx<<<g, 256>>>(W_ih, b_ih);
    gru_recur<<<NBLK, RTHREADS>>>(W_hh, b_hh, out);
}